// round 1
// baseline (speedup 1.0000x reference)
#include <cuda_runtime.h>

// SSIM loss, fused single-pass per tile.
// Shapes fixed by the problem: (16,31,256,256) fp32 x2 inputs, scalar fp32 out.

#define IMG   256
#define OUT   246          // 256 - 11 + 1
#define TW    32
#define TH    32
#define HALO  10
#define IN_W  (TW + HALO)  // 42
#define IN_H  (TH + HALO)  // 42
#define PADX  44           // row stride for input tiles (16B-aligned: 176B)
#define PADH  36           // row stride for moment arrays (144B, 16B-aligned)
#define NIMG  496
#define NTOT  30015936.0   // 496 * 246 * 246

// 11-tap Gaussian, sigma=1.5, normalized (computed in high precision).
// Compile-time constants -> FFMA-imm (rt_SMSP=1, 2x fp32 throughput).
__device__ constexpr float GW[11] = {
    0.00102838f, 0.00759874f, 0.03600078f, 0.10936071f, 0.21300555f,
    0.26601174f,
    0.21300555f, 0.10936071f, 0.03600078f, 0.00759874f, 0.00102838f
};

#define C1 1.0e-4f
#define C2 9.0e-4f

__device__ double g_acc;

__global__ void ssim_zero_kernel() { g_acc = 0.0; }

__global__ __launch_bounds__(256)
void ssim_main_kernel(const float* __restrict__ X, const float* __restrict__ Y) {
    __shared__ __align__(16) float sx[IN_H][PADX];
    __shared__ __align__(16) float sy[IN_H][PADX];
    __shared__ __align__(16) float hm[5][IN_H][PADH];  // hx,hy,hxx,hyy,hxy
    __shared__ float red[8];

    const int tid = threadIdx.x;
    const int C0  = blockIdx.x * TW;
    const int R0  = blockIdx.y * TH;
    const int img = blockIdx.z;

    const float* __restrict__ xi = X + (size_t)img * IMG * IMG;
    const float* __restrict__ yi = Y + (size_t)img * IMG * IMG;

    // ---- Phase 1: load haloed tile (zero-pad out of range; OOB outputs discarded later)
    for (int i = tid; i < IN_H * IN_W; i += 256) {
        int r = i / IN_W, c = i - r * IN_W;
        int gr = R0 + r, gc = C0 + c;
        float xv = 0.f, yv = 0.f;
        if (gr < IMG && gc < IMG) {
            xv = __ldg(&xi[gr * IMG + gc]);
            yv = __ldg(&yi[gr * IMG + gc]);
        }
        sx[r][c] = xv;
        sy[r][c] = yv;
    }
    // pad columns 42..43 so float4 window loads stay in-bounds
    if (tid < IN_H * 2) {
        int r = tid >> 1, c = IN_W + (tid & 1);
        sx[r][c] = 0.f;
        sy[r][c] = 0.f;
    }
    __syncthreads();

    // ---- Phase 2: horizontal blur of 5 moments. 42 rows x 8 runs of 4 cols = 336 runs.
    for (int i = tid; i < IN_H * (TW / 4); i += 256) {
        const int r  = i >> 3;
        const int c0 = (i & 7) * 4;

        float xv[16], yv[16];
        #pragma unroll
        for (int q = 0; q < 4; q++) {
            float4 a = *(const float4*)&sx[r][c0 + 4 * q];
            xv[4 * q + 0] = a.x; xv[4 * q + 1] = a.y;
            xv[4 * q + 2] = a.z; xv[4 * q + 3] = a.w;
            float4 b = *(const float4*)&sy[r][c0 + 4 * q];
            yv[4 * q + 0] = b.x; yv[4 * q + 1] = b.y;
            yv[4 * q + 2] = b.z; yv[4 * q + 3] = b.w;
        }

        // hx
        {
            float a0 = 0.f, a1 = 0.f, a2 = 0.f, a3 = 0.f;
            #pragma unroll
            for (int k = 0; k < 11; k++) {
                a0 += GW[k] * xv[k];     a1 += GW[k] * xv[k + 1];
                a2 += GW[k] * xv[k + 2]; a3 += GW[k] * xv[k + 3];
            }
            hm[0][r][c0] = a0; hm[0][r][c0 + 1] = a1;
            hm[0][r][c0 + 2] = a2; hm[0][r][c0 + 3] = a3;
        }
        // hy
        {
            float a0 = 0.f, a1 = 0.f, a2 = 0.f, a3 = 0.f;
            #pragma unroll
            for (int k = 0; k < 11; k++) {
                a0 += GW[k] * yv[k];     a1 += GW[k] * yv[k + 1];
                a2 += GW[k] * yv[k + 2]; a3 += GW[k] * yv[k + 3];
            }
            hm[1][r][c0] = a0; hm[1][r][c0 + 1] = a1;
            hm[1][r][c0 + 2] = a2; hm[1][r][c0 + 3] = a3;
        }
        // hxx
        {
            float sq[14];
            #pragma unroll
            for (int k = 0; k < 14; k++) sq[k] = xv[k] * xv[k];
            float a0 = 0.f, a1 = 0.f, a2 = 0.f, a3 = 0.f;
            #pragma unroll
            for (int k = 0; k < 11; k++) {
                a0 += GW[k] * sq[k];     a1 += GW[k] * sq[k + 1];
                a2 += GW[k] * sq[k + 2]; a3 += GW[k] * sq[k + 3];
            }
            hm[2][r][c0] = a0; hm[2][r][c0 + 1] = a1;
            hm[2][r][c0 + 2] = a2; hm[2][r][c0 + 3] = a3;
        }
        // hyy
        {
            float sq[14];
            #pragma unroll
            for (int k = 0; k < 14; k++) sq[k] = yv[k] * yv[k];
            float a0 = 0.f, a1 = 0.f, a2 = 0.f, a3 = 0.f;
            #pragma unroll
            for (int k = 0; k < 11; k++) {
                a0 += GW[k] * sq[k];     a1 += GW[k] * sq[k + 1];
                a2 += GW[k] * sq[k + 2]; a3 += GW[k] * sq[k + 3];
            }
            hm[3][r][c0] = a0; hm[3][r][c0 + 1] = a1;
            hm[3][r][c0 + 2] = a2; hm[3][r][c0 + 3] = a3;
        }
        // hxy
        {
            float sq[14];
            #pragma unroll
            for (int k = 0; k < 14; k++) sq[k] = xv[k] * yv[k];
            float a0 = 0.f, a1 = 0.f, a2 = 0.f, a3 = 0.f;
            #pragma unroll
            for (int k = 0; k < 11; k++) {
                a0 += GW[k] * sq[k];     a1 += GW[k] * sq[k + 1];
                a2 += GW[k] * sq[k + 2]; a3 += GW[k] * sq[k + 3];
            }
            hm[4][r][c0] = a0; hm[4][r][c0 + 1] = a1;
            hm[4][r][c0 + 2] = a2; hm[4][r][c0 + 3] = a3;
        }
    }
    __syncthreads();

    // ---- Phase 3: vertical blur + SSIM. One run per thread: col = tid&31, rows r0..r0+3.
    const int c  = tid & 31;
    const int r0 = (tid >> 5) * 4;

    float res[5][4];
    #pragma unroll
    for (int m = 0; m < 5; m++) {
        float v[14];
        #pragma unroll
        for (int k = 0; k < 14; k++) v[k] = hm[m][r0 + k][c];
        float b0 = 0.f, b1 = 0.f, b2 = 0.f, b3 = 0.f;
        #pragma unroll
        for (int k = 0; k < 11; k++) {
            b0 += GW[k] * v[k];     b1 += GW[k] * v[k + 1];
            b2 += GW[k] * v[k + 2]; b3 += GW[k] * v[k + 3];
        }
        res[m][0] = b0; res[m][1] = b1; res[m][2] = b2; res[m][3] = b3;
    }

    float lsum = 0.f;
    const int oc = C0 + c;
    #pragma unroll
    for (int j = 0; j < 4; j++) {
        int orow = R0 + r0 + j;
        if (orow < OUT && oc < OUT) {
            float mx  = res[0][j], my  = res[1][j];
            float mxx = res[2][j], myy = res[3][j], mxy = res[4][j];
            float vx  = mxx - mx * mx;
            float vy  = myy - my * my;
            float cov = mxy - mx * my;
            float num = (2.f * mx * my + C1) * (2.f * cov + C2);
            float den = (mx * mx + my * my + C1) * (vx + vy + C2);
            lsum += num / den;
        }
    }

    // ---- block reduce -> global double accumulator
    #pragma unroll
    for (int o = 16; o > 0; o >>= 1)
        lsum += __shfl_xor_sync(0xffffffffu, lsum, o);
    if ((tid & 31) == 0) red[tid >> 5] = lsum;
    __syncthreads();
    if (tid == 0) {
        float s = 0.f;
        #pragma unroll
        for (int w = 0; w < 8; w++) s += red[w];
        atomicAdd(&g_acc, (double)s);
    }
}

__global__ void ssim_final_kernel(float* __restrict__ out) {
    out[0] = (float)(1.0 - g_acc / NTOT);
}

extern "C" void kernel_launch(void* const* d_in, const int* in_sizes, int n_in,
                              void* d_out, int out_size) {
    const float* X = (const float*)d_in[0];
    const float* Y = (const float*)d_in[1];
    float* out = (float*)d_out;

    ssim_zero_kernel<<<1, 1>>>();
    dim3 grid((OUT + TW - 1) / TW, (OUT + TH - 1) / TH, NIMG);  // 8 x 8 x 496
    ssim_main_kernel<<<grid, 256>>>(X, Y);
    ssim_final_kernel<<<1, 1>>>(out);
}

// round 2
// speedup vs baseline: 1.0558x; 1.0558x over previous
#include <cuda_runtime.h>

// SSIM loss, fused single-pass per tile, f32x2-packed blur chains.
// Shapes fixed: (16,31,256,256) fp32 x2 inputs, scalar fp32 out.

#define IMG   256
#define OUT   246          // 256 - 11 + 1
#define TW    32
#define TH    32
#define HALO  10
#define IN_W  (TW + HALO)  // 42
#define IN_H  (TH + HALO)  // 42
#define PADX  44           // row stride (u64 elems) for packed input tile
#define PADH  36           // row stride for moment arrays
#define NIMG  496
#define NTOT  30015936.0   // 496 * 246 * 246

typedef unsigned long long u64;

// 11-tap Gaussian, sigma=1.5, normalized.
__device__ constexpr float GW[11] = {
    0.00102838f, 0.00759874f, 0.03600078f, 0.10936071f, 0.21300555f,
    0.26601174f,
    0.21300555f, 0.10936071f, 0.03600078f, 0.00759874f, 0.00102838f
};

#define C1 1.0e-4f
#define C2 9.0e-4f

// ---- packed f32x2 helpers (Blackwell FFMA2 path, PTX-only) ----
__device__ __forceinline__ u64 pk2(float x, float y) {
    u64 r; asm("mov.b64 %0, {%1, %2};" : "=l"(r) : "f"(x), "f"(y)); return r;
}
__device__ __forceinline__ void unpk(u64 p, float& x, float& y) {
    asm("mov.b64 {%0, %1}, %2;" : "=f"(x), "=f"(y) : "l"(p));
}
__device__ __forceinline__ u64 f2fma(u64 a, u64 b, u64 c) {
    u64 d; asm("fma.rn.f32x2 %0, %1, %2, %3;" : "=l"(d) : "l"(a), "l"(b), "l"(c)); return d;
}
__device__ __forceinline__ u64 f2mul(u64 a, u64 b) {
    u64 d; asm("mul.rn.f32x2 %0, %1, %2;" : "=l"(d) : "l"(a), "l"(b)); return d;
}

__device__ double g_acc;

__global__ void ssim_zero_kernel() { g_acc = 0.0; }

__global__ __launch_bounds__(256)
void ssim_main_kernel(const float* __restrict__ X, const float* __restrict__ Y) {
    __shared__ __align__(16) u64   sxy[IN_H][PADX];   // packed {x, y}
    __shared__ __align__(16) u64   hm01[IN_H][PADH];  // packed {hx, hy}
    __shared__ __align__(16) u64   hm23[IN_H][PADH];  // packed {hxx, hyy}
    __shared__ __align__(16) float hm4 [IN_H][PADH];  // hxy
    __shared__ float red[8];

    const int tid = threadIdx.x;
    const int C0  = blockIdx.x * TW;
    const int R0  = blockIdx.y * TH;
    const int img = blockIdx.z;

    const float* __restrict__ xi = X + (size_t)img * IMG * IMG;
    const float* __restrict__ yi = Y + (size_t)img * IMG * IMG;

    // packed weight pairs (hoisted, built from immediates)
    u64 W2[11];
    #pragma unroll
    for (int k = 0; k < 11; k++) W2[k] = pk2(GW[k], GW[k]);

    // ---- Phase 1: load haloed tile, packed {x,y}
    for (int i = tid; i < IN_H * IN_W; i += 256) {
        int r = i / IN_W, cc = i - r * IN_W;
        int gr = R0 + r, gc = C0 + cc;
        float xv = 0.f, yv = 0.f;
        if (gr < IMG && gc < IMG) {
            xv = __ldg(&xi[gr * IMG + gc]);
            yv = __ldg(&yi[gr * IMG + gc]);
        }
        sxy[r][cc] = pk2(xv, yv);
    }
    if (tid < IN_H * 2) {               // pad cols 42..43 for window loads
        int r = tid >> 1, cc = IN_W + (tid & 1);
        sxy[r][cc] = 0ull;
    }
    __syncthreads();

    // ---- Phase 2: horizontal blur. 42 rows x 8 runs of 4 outputs.
    for (int i = tid; i < IN_H * (TW / 4); i += 256) {
        const int r  = i >> 3;
        const int c0 = (i & 7) * 4;

        u64 p[14];
        {
            const ulonglong2* src = (const ulonglong2*)&sxy[r][c0];
            #pragma unroll
            for (int j = 0; j < 7; j++) {
                ulonglong2 t = src[j];
                p[2 * j] = t.x; p[2 * j + 1] = t.y;
            }
        }

        u64  a0 = 0, a1 = 0, a2 = 0, a3 = 0;   // {hx,hy}
        u64  b0 = 0, b1 = 0, b2 = 0, b3 = 0;   // {hxx,hyy}
        float s0 = 0.f, s1 = 0.f, s2 = 0.f, s3 = 0.f;  // hxy
        #pragma unroll
        for (int k = 0; k < 14; k++) {
            float xk, yk; unpk(p[k], xk, yk);
            u64   sq = f2mul(p[k], p[k]);
            float xy = xk * yk;
            if (k <= 10)            { a0 = f2fma(p[k], W2[k],     a0); b0 = f2fma(sq, W2[k],     b0); s0 += GW[k]     * xy; }
            if (k >= 1 && k <= 11)  { a1 = f2fma(p[k], W2[k - 1], a1); b1 = f2fma(sq, W2[k - 1], b1); s1 += GW[k - 1] * xy; }
            if (k >= 2 && k <= 12)  { a2 = f2fma(p[k], W2[k - 2], a2); b2 = f2fma(sq, W2[k - 2], b2); s2 += GW[k - 2] * xy; }
            if (k >= 3)             { a3 = f2fma(p[k], W2[k - 3], a3); b3 = f2fma(sq, W2[k - 3], b3); s3 += GW[k - 3] * xy; }
        }

        *(ulonglong2*)&hm01[r][c0]     = make_ulonglong2(a0, a1);
        *(ulonglong2*)&hm01[r][c0 + 2] = make_ulonglong2(a2, a3);
        *(ulonglong2*)&hm23[r][c0]     = make_ulonglong2(b0, b1);
        *(ulonglong2*)&hm23[r][c0 + 2] = make_ulonglong2(b2, b3);
        *(float4*)&hm4[r][c0] = make_float4(s0, s1, s2, s3);
    }
    __syncthreads();

    // ---- Phase 3: vertical blur + SSIM. col = tid&31, rows r0..r0+3.
    const int c  = tid & 31;
    const int r0 = (tid >> 5) * 4;

    u64 m01[4], m23[4];
    float m4[4];
    {   // {hx,hy} pack
        u64 a0 = 0, a1 = 0, a2 = 0, a3 = 0;
        #pragma unroll
        for (int k = 0; k < 14; k++) {
            u64 v = hm01[r0 + k][c];
            if (k <= 10)           a0 = f2fma(v, W2[k],     a0);
            if (k >= 1 && k <= 11) a1 = f2fma(v, W2[k - 1], a1);
            if (k >= 2 && k <= 12) a2 = f2fma(v, W2[k - 2], a2);
            if (k >= 3)            a3 = f2fma(v, W2[k - 3], a3);
        }
        m01[0] = a0; m01[1] = a1; m01[2] = a2; m01[3] = a3;
    }
    {   // {hxx,hyy} pack
        u64 a0 = 0, a1 = 0, a2 = 0, a3 = 0;
        #pragma unroll
        for (int k = 0; k < 14; k++) {
            u64 v = hm23[r0 + k][c];
            if (k <= 10)           a0 = f2fma(v, W2[k],     a0);
            if (k >= 1 && k <= 11) a1 = f2fma(v, W2[k - 1], a1);
            if (k >= 2 && k <= 12) a2 = f2fma(v, W2[k - 2], a2);
            if (k >= 3)            a3 = f2fma(v, W2[k - 3], a3);
        }
        m23[0] = a0; m23[1] = a1; m23[2] = a2; m23[3] = a3;
    }
    {   // hxy scalar
        float a0 = 0.f, a1 = 0.f, a2 = 0.f, a3 = 0.f;
        #pragma unroll
        for (int k = 0; k < 14; k++) {
            float v = hm4[r0 + k][c];
            if (k <= 10)           a0 += GW[k]     * v;
            if (k >= 1 && k <= 11) a1 += GW[k - 1] * v;
            if (k >= 2 && k <= 12) a2 += GW[k - 2] * v;
            if (k >= 3)            a3 += GW[k - 3] * v;
        }
        m4[0] = a0; m4[1] = a1; m4[2] = a2; m4[3] = a3;
    }

    float lsum = 0.f;
    const int oc = C0 + c;
    #pragma unroll
    for (int j = 0; j < 4; j++) {
        int orow = R0 + r0 + j;
        if (orow < OUT && oc < OUT) {
            float mx, my;  unpk(m01[j], mx, my);
            float mxx, myy; unpk(m23[j], mxx, myy);
            float mxy = m4[j];
            float vx  = mxx - mx * mx;
            float vy  = myy - my * my;
            float cov = mxy - mx * my;
            float num = (2.f * mx * my + C1) * (2.f * cov + C2);
            float den = (mx * mx + my * my + C1) * (vx + vy + C2);
            lsum += __fdividef(num, den);
        }
    }

    // ---- block reduce -> global double accumulator
    #pragma unroll
    for (int o = 16; o > 0; o >>= 1)
        lsum += __shfl_xor_sync(0xffffffffu, lsum, o);
    if ((tid & 31) == 0) red[tid >> 5] = lsum;
    __syncthreads();
    if (tid == 0) {
        float s = 0.f;
        #pragma unroll
        for (int w = 0; w < 8; w++) s += red[w];
        atomicAdd(&g_acc, (double)s);
    }
}

__global__ void ssim_final_kernel(float* __restrict__ out) {
    out[0] = (float)(1.0 - g_acc / NTOT);
}

extern "C" void kernel_launch(void* const* d_in, const int* in_sizes, int n_in,
                              void* d_out, int out_size) {
    const float* X = (const float*)d_in[0];
    const float* Y = (const float*)d_in[1];
    float* out = (float*)d_out;

    ssim_zero_kernel<<<1, 1>>>();
    dim3 grid((OUT + TW - 1) / TW, (OUT + TH - 1) / TH, NIMG);  // 8 x 8 x 496
    ssim_main_kernel<<<grid, 256>>>(X, Y);
    ssim_final_kernel<<<1, 1>>>(out);
}